// round 3
// baseline (speedup 1.0000x reference)
#include <cuda_runtime.h>
#include <cstdint>

#define H   2048
#define I1  1024        // inter
#define I2  2048        // 2*inter
#define E   32
#define MAXT 8192
#define MAXPAIR (2*MAXT)
#define TM 64
#define TN 64
#define TK 16
#define MAXTILES 320    // >= 2*T/TM + E = 288

// ---------------- device scratch (static: no allocations allowed) ----------------
__device__ float g_h[MAXPAIR * I1];          // 64 MB swiglu outputs per (token,expert) pair
__device__ float g_logits[MAXT * E];
__device__ int   g_counts[E];
__device__ int   g_cursor[E];
__device__ int   g_offsets[E];
__device__ int   g_tok_e[MAXT * 2];
__device__ float g_tok_g[MAXT * 2];
__device__ int   g_pair_tok[MAXPAIR];
__device__ float g_pair_gate[MAXPAIR];
__device__ int   g_tile_expert[MAXTILES];
__device__ int   g_tile_rowbase[MAXTILES];
__device__ int   g_tile_pairbase[MAXTILES];
__device__ int   g_n_tiles;

// ---------------- packed f32x2 helpers (Blackwell FFMA2 path) ----------------
#define FMA2(d,a,b) asm("fma.rn.f32x2 %0, %1, %2, %0;" : "+l"(d) : "l"(a), "l"(b))

__device__ __forceinline__ unsigned long long packdup(float f) {
    unsigned long long r;
    asm("mov.b64 %0, {%1, %1};" : "=l"(r) : "f"(f));
    return r;
}
__device__ __forceinline__ void unpack2(unsigned long long d, float& lo, float& hi) {
    asm("mov.b64 {%0, %1}, %2;" : "=f"(lo), "=f"(hi) : "l"(d));
}

// ---------------- init: zero small control arrays ----------------
__global__ void init_kernel() {
    int i = threadIdx.x;
    if (i < E) { g_counts[i] = 0; g_cursor[i] = 0; }
    if (i == 0) g_n_tiles = 0;
}

// ---------------- router GEMM: logits[T,32] = x @ gate_w^T + gate_b ----------------
__global__ __launch_bounds__(256) void router_gemm(const float* __restrict__ x,
                                                   const float* __restrict__ gw,
                                                   const float* __restrict__ gb) {
    __shared__ __align__(16) float xs[32][36];
    __shared__ __align__(16) float ws[32][36];
    int tid = threadIdx.x;
    int tx = tid & 7;          // expert group: 4 experts each
    int ty = tid >> 3;         // token 0..31
    int tbase = blockIdx.x * 32;
    int lrow = tid >> 3;       // 0..31 (load row)
    int lk4  = (tid & 7) * 4;  // 0..28

    float acc[4] = {0.f, 0.f, 0.f, 0.f};
    const float* xp = x  + (size_t)(tbase + lrow) * H + lk4;
    const float* wp = gw + (size_t)lrow * H + lk4;

    for (int kb = 0; kb < H; kb += 32) {
        float4 xv = *(const float4*)(xp + kb);
        float4 wv = *(const float4*)(wp + kb);
        *(float4*)&xs[lrow][lk4] = xv;
        ws[lk4 + 0][lrow] = wv.x;
        ws[lk4 + 1][lrow] = wv.y;
        ws[lk4 + 2][lrow] = wv.z;
        ws[lk4 + 3][lrow] = wv.w;
        __syncthreads();
#pragma unroll
        for (int k = 0; k < 32; ++k) {
            float xv1 = xs[ty][k];
            float4 w4 = *(const float4*)&ws[k][tx * 4];
            acc[0] = fmaf(xv1, w4.x, acc[0]);
            acc[1] = fmaf(xv1, w4.y, acc[1]);
            acc[2] = fmaf(xv1, w4.z, acc[2]);
            acc[3] = fmaf(xv1, w4.w, acc[3]);
        }
        __syncthreads();
    }
    int t = tbase + ty;
#pragma unroll
    for (int j = 0; j < 4; ++j)
        g_logits[t * E + tx * 4 + j] = acc[j] + gb[tx * 4 + j];
}

// ---------------- softmax + top-2 per token; count tokens per expert ----------------
__global__ void topk_kernel(int T) {
    int warp = (blockIdx.x * blockDim.x + threadIdx.x) >> 5;
    int lane = threadIdx.x & 31;
    if (warp >= T) return;
    float l = g_logits[warp * E + lane];

    float m = l;
#pragma unroll
    for (int o = 16; o; o >>= 1) m = fmaxf(m, __shfl_xor_sync(0xffffffffu, m, o));
    float p = __expf(l - m);
    float s = p;
#pragma unroll
    for (int o = 16; o; o >>= 1) s += __shfl_xor_sync(0xffffffffu, s, o);
    float prob = p / s;

    // top-1 (tie -> lower index, matching lax.top_k)
    float v = prob; int idx = lane;
#pragma unroll
    for (int o = 16; o; o >>= 1) {
        float vo = __shfl_xor_sync(0xffffffffu, v, o);
        int   io = __shfl_xor_sync(0xffffffffu, idx, o);
        if (vo > v || (vo == v && io < idx)) { v = vo; idx = io; }
    }
    int e0 = idx; float g0 = v;

    float v2 = (lane == e0) ? -1.0f : prob; int idx2 = lane;
#pragma unroll
    for (int o = 16; o; o >>= 1) {
        float vo = __shfl_xor_sync(0xffffffffu, v2, o);
        int   io = __shfl_xor_sync(0xffffffffu, idx2, o);
        if (vo > v2 || (vo == v2 && io < idx2)) { v2 = vo; idx2 = io; }
    }
    int e1 = idx2; float g1 = v2;

    if (lane == 0) {
        g_tok_e[warp * 2 + 0] = e0; g_tok_g[warp * 2 + 0] = g0;
        g_tok_e[warp * 2 + 1] = e1; g_tok_g[warp * 2 + 1] = g1;
        atomicAdd(&g_counts[e0], 1);
        atomicAdd(&g_counts[e1], 1);
    }
}

// ---------------- scan: expert offsets + tile list ----------------
__global__ void scan_kernel() {
    if (threadIdx.x != 0) return;
    int off = 0, nt = 0;
    for (int e = 0; e < E; ++e) {
        g_offsets[e] = off;
        int c = g_counts[e];
        for (int rb = 0; rb < c; rb += TM) {
            g_tile_expert[nt]   = e;
            g_tile_rowbase[nt]  = rb;
            g_tile_pairbase[nt] = off + rb;
            nt++;
        }
        off += c;
    }
    g_n_tiles = nt;
}

// ---------------- scatter tokens into per-expert contiguous pair lists ----------------
__global__ void scatter_kernel(int T) {
    int t = blockIdx.x * blockDim.x + threadIdx.x;
    if (t >= T) return;
#pragma unroll
    for (int j = 0; j < 2; ++j) {
        int e = g_tok_e[t * 2 + j];
        int pos = g_offsets[e] + atomicAdd(&g_cursor[e], 1);
        g_pair_tok[pos]  = t;
        g_pair_gate[pos] = g_tok_g[t * 2 + j];
    }
}

// ---------------- fc1: gathered GEMM [rows,2I] = X[tok] @ W1_e^T, fused swiglu -> g_h ----------------
__global__ __launch_bounds__(256) void fc1_kernel(const float* __restrict__ x,
                                                  const float* __restrict__ w1,
                                                  const float* __restrict__ b1) {
    int tile = blockIdx.x;
    if (tile >= g_n_tiles) return;
    int e         = g_tile_expert[tile];
    int rowbase   = g_tile_rowbase[tile];
    int pair_base = g_tile_pairbase[tile];
    int rows = g_counts[e] - rowbase; if (rows > TM) rows = TM;
    int nbase = blockIdx.y * TN;

    __shared__ __align__(16) float a_s[TK][TM + 4];
    __shared__ __align__(16) float b_s[TK][TN + 2];

    int tid = threadIdx.x;
    int tx = tid & 15, ty = tid >> 4;
    int lrow = tid >> 2, lk4 = (tid & 3) << 2;

    int arow = (lrow < rows) ? lrow : 0;
    int tok  = g_pair_tok[pair_base + arow];
    const float* aptr = x  + (size_t)tok * H + lk4;
    const float* bptr = w1 + ((size_t)e * I2 + (nbase + lrow)) * H + lk4;

    unsigned long long acc[4][2];
#pragma unroll
    for (int i = 0; i < 4; ++i) { acc[i][0] = 0ull; acc[i][1] = 0ull; }

    float4 areg = *(const float4*)aptr;
    float4 breg = *(const float4*)bptr;

    const int NK = H / TK;
    for (int kc = 0; kc < NK; ++kc) {
        a_s[lk4 + 0][lrow] = areg.x; a_s[lk4 + 1][lrow] = areg.y;
        a_s[lk4 + 2][lrow] = areg.z; a_s[lk4 + 3][lrow] = areg.w;
        b_s[lk4 + 0][lrow] = breg.x; b_s[lk4 + 1][lrow] = breg.y;
        b_s[lk4 + 2][lrow] = breg.z; b_s[lk4 + 3][lrow] = breg.w;
        __syncthreads();
        if (kc + 1 < NK) {
            areg = *(const float4*)(aptr + (kc + 1) * TK);
            breg = *(const float4*)(bptr + (kc + 1) * TK);
        }
#pragma unroll
        for (int k = 0; k < TK; ++k) {
            float4 av = *(const float4*)&a_s[k][ty * 4];
            const unsigned long long* brow = (const unsigned long long*)&b_s[k][0];
            unsigned long long bv0 = brow[tx * 2], bv1 = brow[tx * 2 + 1];
            unsigned long long a0 = packdup(av.x), a1 = packdup(av.y);
            unsigned long long a2 = packdup(av.z), a3 = packdup(av.w);
            FMA2(acc[0][0], a0, bv0); FMA2(acc[0][1], a0, bv1);
            FMA2(acc[1][0], a1, bv0); FMA2(acc[1][1], a1, bv1);
            FMA2(acc[2][0], a2, bv0); FMA2(acc[2][1], a2, bv1);
            FMA2(acc[3][0], a3, bv0); FMA2(acc[3][1], a3, bv1);
        }
        __syncthreads();
    }

    const float* b1e = b1 + e * I2;
#pragma unroll
    for (int i = 0; i < 4; ++i) {
        int lm = ty * 4 + i;
        if (lm >= rows) continue;
        int pair = pair_base + lm;
#pragma unroll
        for (int jj = 0; jj < 2; ++jj) {
            float zg, zl;
            unpack2(acc[i][jj], zg, zl);
            int ncol = nbase + tx * 4 + jj * 2;        // even column -> glu path
            zg += b1e[ncol];
            zl += b1e[ncol + 1];
            zg = fminf(zg, 7.0f);
            zl = fminf(fmaxf(zl, -7.0f), 7.0f);
            float hv = zg * (1.0f / (1.0f + __expf(-1.702f * zg))) * (zl + 1.0f);
            g_h[pair * I1 + (ncol >> 1)] = hv;
        }
    }
}

// ---------------- fc2: [rows,H] = h @ W2_e^T (+b2), scaled by gate, atomic-scatter to out ----------------
__global__ __launch_bounds__(256) void fc2_kernel(const float* __restrict__ w2,
                                                  const float* __restrict__ b2,
                                                  float* __restrict__ out,
                                                  int total_pairs) {
    int tile = blockIdx.x;
    if (tile >= g_n_tiles) return;
    int e         = g_tile_expert[tile];
    int rowbase   = g_tile_rowbase[tile];
    int pair_base = g_tile_pairbase[tile];
    int rows = g_counts[e] - rowbase; if (rows > TM) rows = TM;
    int nbase = blockIdx.y * TN;

    __shared__ __align__(16) float a_s[TK][TM + 4];
    __shared__ __align__(16) float b_s[TK][TN + 2];

    int tid = threadIdx.x;
    int tx = tid & 15, ty = tid >> 4;
    int lrow = tid >> 2, lk4 = (tid & 3) << 2;

    int prow = pair_base + lrow;
    if (prow >= total_pairs) prow = total_pairs - 1;
    const float* aptr = g_h + (size_t)prow * I1 + lk4;
    const float* bptr = w2  + ((size_t)e * H + (nbase + lrow)) * I1 + lk4;

    unsigned long long acc[4][2];
#pragma unroll
    for (int i = 0; i < 4; ++i) { acc[i][0] = 0ull; acc[i][1] = 0ull; }

    float4 areg = *(const float4*)aptr;
    float4 breg = *(const float4*)bptr;

    const int NK = I1 / TK;
    for (int kc = 0; kc < NK; ++kc) {
        a_s[lk4 + 0][lrow] = areg.x; a_s[lk4 + 1][lrow] = areg.y;
        a_s[lk4 + 2][lrow] = areg.z; a_s[lk4 + 3][lrow] = areg.w;
        b_s[lk4 + 0][lrow] = breg.x; b_s[lk4 + 1][lrow] = breg.y;
        b_s[lk4 + 2][lrow] = breg.z; b_s[lk4 + 3][lrow] = breg.w;
        __syncthreads();
        if (kc + 1 < NK) {
            areg = *(const float4*)(aptr + (kc + 1) * TK);
            breg = *(const float4*)(bptr + (kc + 1) * TK);
        }
#pragma unroll
        for (int k = 0; k < TK; ++k) {
            float4 av = *(const float4*)&a_s[k][ty * 4];
            const unsigned long long* brow = (const unsigned long long*)&b_s[k][0];
            unsigned long long bv0 = brow[tx * 2], bv1 = brow[tx * 2 + 1];
            unsigned long long a0 = packdup(av.x), a1 = packdup(av.y);
            unsigned long long a2 = packdup(av.z), a3 = packdup(av.w);
            FMA2(acc[0][0], a0, bv0); FMA2(acc[0][1], a0, bv1);
            FMA2(acc[1][0], a1, bv0); FMA2(acc[1][1], a1, bv1);
            FMA2(acc[2][0], a2, bv0); FMA2(acc[2][1], a2, bv1);
            FMA2(acc[3][0], a3, bv0); FMA2(acc[3][1], a3, bv1);
        }
        __syncthreads();
    }

    const float* b2e = b2 + e * H;
#pragma unroll
    for (int i = 0; i < 4; ++i) {
        int lm = ty * 4 + i;
        if (lm >= rows) continue;
        int pair = pair_base + lm;
        int tok  = g_pair_tok[pair];
        float gate = g_pair_gate[pair];
        float* orow = out + (size_t)tok * H;
#pragma unroll
        for (int jj = 0; jj < 2; ++jj) {
            float y0, y1;
            unpack2(acc[i][jj], y0, y1);
            int ncol = nbase + tx * 4 + jj * 2;
            atomicAdd(orow + ncol,     gate * (y0 + b2e[ncol]));
            atomicAdd(orow + ncol + 1, gate * (y1 + b2e[ncol + 1]));
        }
    }
}

// ---------------- launch ----------------
extern "C" void kernel_launch(void* const* d_in, const int* in_sizes, int n_in,
                              void* d_out, int out_size) {
    const float* x  = (const float*)d_in[0];
    const float* gw = (const float*)d_in[1];
    const float* gb = (const float*)d_in[2];
    const float* w1 = (const float*)d_in[3];
    const float* b1 = (const float*)d_in[4];
    const float* w2 = (const float*)d_in[5];
    const float* b2 = (const float*)d_in[6];
    float* out = (float*)d_out;
    int T = in_sizes[0] / H;   // 8192

    cudaMemsetAsync(d_out, 0, (size_t)out_size * sizeof(float));
    init_kernel<<<1, 64>>>();
    router_gemm<<<T / 32, 256>>>(x, gw, gb);
    topk_kernel<<<(T + 7) / 8, 256>>>(T);
    scan_kernel<<<1, 32>>>();
    scatter_kernel<<<(T + 255) / 256, 256>>>(T);

    dim3 g1(MAXTILES, I2 / TN);   // (320, 32)
    fc1_kernel<<<g1, 256>>>(x, w1, b1);
    dim3 g2(MAXTILES, H / TN);    // (320, 32)
    fc2_kernel<<<g2, 256>>>(w2, b2, out, 2 * T);
}

// round 4
// speedup vs baseline: 1.0011x; 1.0011x over previous
#include <cuda_runtime.h>
#include <cstdint>

#define H   2048
#define I1  1024        // inter
#define I2  2048        // 2*inter
#define E   32
#define MAXT 8192
#define MAXPAIR (2*MAXT)
#define TM 64
#define TN 64
#define TK 16
#define MAXTILES 320    // >= 2*T/TM + E = 288

// ---------------- device scratch (static: no allocations allowed) ----------------
__device__ float g_h[MAXPAIR * I1];          // 64 MB swiglu outputs per (token,expert) pair
__device__ float g_logits[MAXT * E];
__device__ int   g_counts[E];
__device__ int   g_cursor[E];
__device__ int   g_offsets[E];
__device__ int   g_tok_e[MAXT * 2];
__device__ float g_tok_g[MAXT * 2];
__device__ int   g_pair_tok[MAXPAIR];
__device__ float g_pair_gate[MAXPAIR];
__device__ int   g_tile_expert[MAXTILES];
__device__ int   g_tile_rowbase[MAXTILES];
__device__ int   g_tile_pairbase[MAXTILES];
__device__ int   g_n_tiles;

// ---------------- packed f32x2 helpers (Blackwell FFMA2 path) ----------------
#define FMA2(d,a,b) asm("fma.rn.f32x2 %0, %1, %2, %0;" : "+l"(d) : "l"(a), "l"(b))

__device__ __forceinline__ unsigned long long packdup(float f) {
    unsigned long long r;
    asm("mov.b64 %0, {%1, %1};" : "=l"(r) : "f"(f));
    return r;
}
__device__ __forceinline__ void unpack2(unsigned long long d, float& lo, float& hi) {
    asm("mov.b64 {%0, %1}, %2;" : "=f"(lo), "=f"(hi) : "l"(d));
}

// ---------------- init: zero small control arrays ----------------
__global__ void init_kernel() {
    int i = threadIdx.x;
    if (i < E) { g_counts[i] = 0; g_cursor[i] = 0; }
    if (i == 0) g_n_tiles = 0;
}

// ---------------- router GEMM: logits[T,32] = x @ gate_w^T + gate_b ----------------
__global__ __launch_bounds__(256) void router_gemm(const float* __restrict__ x,
                                                   const float* __restrict__ gw,
                                                   const float* __restrict__ gb) {
    __shared__ __align__(16) float xs[32][36];
    __shared__ __align__(16) float ws[32][36];
    int tid = threadIdx.x;
    int tx = tid & 7;          // expert group: 4 experts each
    int ty = tid >> 3;         // token 0..31
    int tbase = blockIdx.x * 32;
    int lrow = tid >> 3;       // 0..31 (load row)
    int lk4  = (tid & 7) * 4;  // 0..28

    float acc[4] = {0.f, 0.f, 0.f, 0.f};
    const float* xp = x  + (size_t)(tbase + lrow) * H + lk4;
    const float* wp = gw + (size_t)lrow * H + lk4;

    for (int kb = 0; kb < H; kb += 32) {
        float4 xv = *(const float4*)(xp + kb);
        float4 wv = *(const float4*)(wp + kb);
        *(float4*)&xs[lrow][lk4] = xv;
        ws[lk4 + 0][lrow] = wv.x;
        ws[lk4 + 1][lrow] = wv.y;
        ws[lk4 + 2][lrow] = wv.z;
        ws[lk4 + 3][lrow] = wv.w;
        __syncthreads();
#pragma unroll
        for (int k = 0; k < 32; ++k) {
            float xv1 = xs[ty][k];
            float4 w4 = *(const float4*)&ws[k][tx * 4];
            acc[0] = fmaf(xv1, w4.x, acc[0]);
            acc[1] = fmaf(xv1, w4.y, acc[1]);
            acc[2] = fmaf(xv1, w4.z, acc[2]);
            acc[3] = fmaf(xv1, w4.w, acc[3]);
        }
        __syncthreads();
    }
    int t = tbase + ty;
#pragma unroll
    for (int j = 0; j < 4; ++j)
        g_logits[t * E + tx * 4 + j] = acc[j] + gb[tx * 4 + j];
}

// ---------------- softmax + top-2 per token; count tokens per expert ----------------
__global__ void topk_kernel(int T) {
    int warp = (blockIdx.x * blockDim.x + threadIdx.x) >> 5;
    int lane = threadIdx.x & 31;
    if (warp >= T) return;
    float l = g_logits[warp * E + lane];

    float m = l;
#pragma unroll
    for (int o = 16; o; o >>= 1) m = fmaxf(m, __shfl_xor_sync(0xffffffffu, m, o));
    float p = __expf(l - m);
    float s = p;
#pragma unroll
    for (int o = 16; o; o >>= 1) s += __shfl_xor_sync(0xffffffffu, s, o);
    float prob = p / s;

    // top-1 (tie -> lower index, matching lax.top_k)
    float v = prob; int idx = lane;
#pragma unroll
    for (int o = 16; o; o >>= 1) {
        float vo = __shfl_xor_sync(0xffffffffu, v, o);
        int   io = __shfl_xor_sync(0xffffffffu, idx, o);
        if (vo > v || (vo == v && io < idx)) { v = vo; idx = io; }
    }
    int e0 = idx; float g0 = v;

    float v2 = (lane == e0) ? -1.0f : prob; int idx2 = lane;
#pragma unroll
    for (int o = 16; o; o >>= 1) {
        float vo = __shfl_xor_sync(0xffffffffu, v2, o);
        int   io = __shfl_xor_sync(0xffffffffu, idx2, o);
        if (vo > v2 || (vo == v2 && io < idx2)) { v2 = vo; idx2 = io; }
    }
    int e1 = idx2; float g1 = v2;

    if (lane == 0) {
        g_tok_e[warp * 2 + 0] = e0; g_tok_g[warp * 2 + 0] = g0;
        g_tok_e[warp * 2 + 1] = e1; g_tok_g[warp * 2 + 1] = g1;
        atomicAdd(&g_counts[e0], 1);
        atomicAdd(&g_counts[e1], 1);
    }
}

// ---------------- scan: expert offsets + tile list ----------------
__global__ void scan_kernel() {
    if (threadIdx.x != 0) return;
    int off = 0, nt = 0;
    for (int e = 0; e < E; ++e) {
        g_offsets[e] = off;
        int c = g_counts[e];
        for (int rb = 0; rb < c; rb += TM) {
            g_tile_expert[nt]   = e;
            g_tile_rowbase[nt]  = rb;
            g_tile_pairbase[nt] = off + rb;
            nt++;
        }
        off += c;
    }
    g_n_tiles = nt;
}

// ---------------- scatter tokens into per-expert contiguous pair lists ----------------
__global__ void scatter_kernel(int T) {
    int t = blockIdx.x * blockDim.x + threadIdx.x;
    if (t >= T) return;
#pragma unroll
    for (int j = 0; j < 2; ++j) {
        int e = g_tok_e[t * 2 + j];
        int pos = g_offsets[e] + atomicAdd(&g_cursor[e], 1);
        g_pair_tok[pos]  = t;
        g_pair_gate[pos] = g_tok_g[t * 2 + j];
    }
}

// ---------------- fc1: gathered GEMM [rows,2I] = X[tok] @ W1_e^T, fused swiglu -> g_h ----------------
__global__ __launch_bounds__(256) void fc1_kernel(const float* __restrict__ x,
                                                  const float* __restrict__ w1,
                                                  const float* __restrict__ b1) {
    int tile = blockIdx.x;
    if (tile >= g_n_tiles) return;
    int e         = g_tile_expert[tile];
    int rowbase   = g_tile_rowbase[tile];
    int pair_base = g_tile_pairbase[tile];
    int rows = g_counts[e] - rowbase; if (rows > TM) rows = TM;
    int nbase = blockIdx.y * TN;

    __shared__ __align__(16) float a_s[TK][TM + 4];
    __shared__ __align__(16) float b_s[TK][TN + 2];

    int tid = threadIdx.x;
    int tx = tid & 15, ty = tid >> 4;
    int lrow = tid >> 2, lk4 = (tid & 3) << 2;

    int arow = (lrow < rows) ? lrow : 0;
    int tok  = g_pair_tok[pair_base + arow];
    const float* aptr = x  + (size_t)tok * H + lk4;
    const float* bptr = w1 + ((size_t)e * I2 + (nbase + lrow)) * H + lk4;

    unsigned long long acc[4][2];
#pragma unroll
    for (int i = 0; i < 4; ++i) { acc[i][0] = 0ull; acc[i][1] = 0ull; }

    float4 areg = *(const float4*)aptr;
    float4 breg = *(const float4*)bptr;

    const int NK = H / TK;
    for (int kc = 0; kc < NK; ++kc) {
        a_s[lk4 + 0][lrow] = areg.x; a_s[lk4 + 1][lrow] = areg.y;
        a_s[lk4 + 2][lrow] = areg.z; a_s[lk4 + 3][lrow] = areg.w;
        b_s[lk4 + 0][lrow] = breg.x; b_s[lk4 + 1][lrow] = breg.y;
        b_s[lk4 + 2][lrow] = breg.z; b_s[lk4 + 3][lrow] = breg.w;
        __syncthreads();
        if (kc + 1 < NK) {
            areg = *(const float4*)(aptr + (kc + 1) * TK);
            breg = *(const float4*)(bptr + (kc + 1) * TK);
        }
#pragma unroll
        for (int k = 0; k < TK; ++k) {
            float4 av = *(const float4*)&a_s[k][ty * 4];
            const unsigned long long* brow = (const unsigned long long*)&b_s[k][0];
            unsigned long long bv0 = brow[tx * 2], bv1 = brow[tx * 2 + 1];
            unsigned long long a0 = packdup(av.x), a1 = packdup(av.y);
            unsigned long long a2 = packdup(av.z), a3 = packdup(av.w);
            FMA2(acc[0][0], a0, bv0); FMA2(acc[0][1], a0, bv1);
            FMA2(acc[1][0], a1, bv0); FMA2(acc[1][1], a1, bv1);
            FMA2(acc[2][0], a2, bv0); FMA2(acc[2][1], a2, bv1);
            FMA2(acc[3][0], a3, bv0); FMA2(acc[3][1], a3, bv1);
        }
        __syncthreads();
    }

    const float* b1e = b1 + e * I2;
#pragma unroll
    for (int i = 0; i < 4; ++i) {
        int lm = ty * 4 + i;
        if (lm >= rows) continue;
        int pair = pair_base + lm;
#pragma unroll
        for (int jj = 0; jj < 2; ++jj) {
            float zg, zl;
            unpack2(acc[i][jj], zg, zl);
            int ncol = nbase + tx * 4 + jj * 2;        // even column -> glu path
            zg += b1e[ncol];
            zl += b1e[ncol + 1];
            zg = fminf(zg, 7.0f);
            zl = fminf(fmaxf(zl, -7.0f), 7.0f);
            float hv = zg * (1.0f / (1.0f + __expf(-1.702f * zg))) * (zl + 1.0f);
            g_h[pair * I1 + (ncol >> 1)] = hv;
        }
    }
}

// ---------------- fc2: [rows,H] = h @ W2_e^T (+b2), scaled by gate, atomic-scatter to out ----------------
__global__ __launch_bounds__(256) void fc2_kernel(const float* __restrict__ w2,
                                                  const float* __restrict__ b2,
                                                  float* __restrict__ out,
                                                  int total_pairs) {
    int tile = blockIdx.x;
    if (tile >= g_n_tiles) return;
    int e         = g_tile_expert[tile];
    int rowbase   = g_tile_rowbase[tile];
    int pair_base = g_tile_pairbase[tile];
    int rows = g_counts[e] - rowbase; if (rows > TM) rows = TM;
    int nbase = blockIdx.y * TN;

    __shared__ __align__(16) float a_s[TK][TM + 4];
    __shared__ __align__(16) float b_s[TK][TN + 2];

    int tid = threadIdx.x;
    int tx = tid & 15, ty = tid >> 4;
    int lrow = tid >> 2, lk4 = (tid & 3) << 2;

    int prow = pair_base + lrow;
    if (prow >= total_pairs) prow = total_pairs - 1;
    const float* aptr = g_h + (size_t)prow * I1 + lk4;
    const float* bptr = w2  + ((size_t)e * H + (nbase + lrow)) * I1 + lk4;

    unsigned long long acc[4][2];
#pragma unroll
    for (int i = 0; i < 4; ++i) { acc[i][0] = 0ull; acc[i][1] = 0ull; }

    float4 areg = *(const float4*)aptr;
    float4 breg = *(const float4*)bptr;

    const int NK = I1 / TK;
    for (int kc = 0; kc < NK; ++kc) {
        a_s[lk4 + 0][lrow] = areg.x; a_s[lk4 + 1][lrow] = areg.y;
        a_s[lk4 + 2][lrow] = areg.z; a_s[lk4 + 3][lrow] = areg.w;
        b_s[lk4 + 0][lrow] = breg.x; b_s[lk4 + 1][lrow] = breg.y;
        b_s[lk4 + 2][lrow] = breg.z; b_s[lk4 + 3][lrow] = breg.w;
        __syncthreads();
        if (kc + 1 < NK) {
            areg = *(const float4*)(aptr + (kc + 1) * TK);
            breg = *(const float4*)(bptr + (kc + 1) * TK);
        }
#pragma unroll
        for (int k = 0; k < TK; ++k) {
            float4 av = *(const float4*)&a_s[k][ty * 4];
            const unsigned long long* brow = (const unsigned long long*)&b_s[k][0];
            unsigned long long bv0 = brow[tx * 2], bv1 = brow[tx * 2 + 1];
            unsigned long long a0 = packdup(av.x), a1 = packdup(av.y);
            unsigned long long a2 = packdup(av.z), a3 = packdup(av.w);
            FMA2(acc[0][0], a0, bv0); FMA2(acc[0][1], a0, bv1);
            FMA2(acc[1][0], a1, bv0); FMA2(acc[1][1], a1, bv1);
            FMA2(acc[2][0], a2, bv0); FMA2(acc[2][1], a2, bv1);
            FMA2(acc[3][0], a3, bv0); FMA2(acc[3][1], a3, bv1);
        }
        __syncthreads();
    }

    const float* b2e = b2 + e * H;
#pragma unroll
    for (int i = 0; i < 4; ++i) {
        int lm = ty * 4 + i;
        if (lm >= rows) continue;
        int pair = pair_base + lm;
        int tok  = g_pair_tok[pair];
        float gate = g_pair_gate[pair];
        float* orow = out + (size_t)tok * H;
#pragma unroll
        for (int jj = 0; jj < 2; ++jj) {
            float y0, y1;
            unpack2(acc[i][jj], y0, y1);
            int ncol = nbase + tx * 4 + jj * 2;
            atomicAdd(orow + ncol,     gate * (y0 + b2e[ncol]));
            atomicAdd(orow + ncol + 1, gate * (y1 + b2e[ncol + 1]));
        }
    }
}

// ---------------- launch ----------------
extern "C" void kernel_launch(void* const* d_in, const int* in_sizes, int n_in,
                              void* d_out, int out_size) {
    const float* x  = (const float*)d_in[0];
    const float* gw = (const float*)d_in[1];
    const float* gb = (const float*)d_in[2];
    const float* w1 = (const float*)d_in[3];
    const float* b1 = (const float*)d_in[4];
    const float* w2 = (const float*)d_in[5];
    const float* b2 = (const float*)d_in[6];
    float* out = (float*)d_out;
    int T = in_sizes[0] / H;   // 8192

    cudaMemsetAsync(d_out, 0, (size_t)out_size * sizeof(float));
    init_kernel<<<1, 64>>>();
    router_gemm<<<T / 32, 256>>>(x, gw, gb);
    topk_kernel<<<(T + 7) / 8, 256>>>(T);
    scan_kernel<<<1, 32>>>();
    scatter_kernel<<<(T + 255) / 256, 256>>>(T);

    dim3 g1(MAXTILES, I2 / TN);   // (320, 32)
    fc1_kernel<<<g1, 256>>>(x, w1, b1);
    dim3 g2(MAXTILES, H / TN);    // (320, 32)
    fc2_kernel<<<g2, 256>>>(w2, b2, out, 2 * T);
}